// round 14
// baseline (speedup 1.0000x reference)
#include <cuda_runtime.h>
#include <cuda_bf16.h>
#include <cuda_fp16.h>
#include <math.h>
#include <stdint.h>

#define NMAX 50000
#define EMAX 800000
#define ETOTAL (EMAX + NMAX)
#define IN_DIM 256
#define HID 64
#define L1C 256
#define OUTD 64
#define SCAN_BLK 1024
#define NSCAN ((NMAX + SCAN_BLK - 1) / SCAN_BLK)

// fp16 GEMM: 3 stages x (A|B) x 2 chunks x [128][24] half = 12288 elems/stage
#define HG_STAGE_ELEMS (4 * 128 * 24)
#define HG_SMEM_BYTES (3 * HG_STAGE_ELEMS * 2)

// ---------------- scratch (device globals; allocation-free) ----------------
__device__ __half g_xrh[(size_t)NMAX * 256];  // layer1 xr fp16 (ld 256); layer2 xr2 (ld 64)
__device__ __half g_xlh[(size_t)NMAX * 256];  // layer1 xl fp16 (ld 256); layer2 xl2 (ld 64)
__device__ __half g_ah[(size_t)NMAX * 256];   // fp16 A (x, then h)
__device__ __half g_bh[512 * 256];            // packed W1 transposed fp16
__device__ __half g_bh2[128 * 64];            // packed W2 transposed fp16
__device__ int   g_deg[NMAX + 1];
__device__ int   g_off[NMAX + 1];
__device__ int   g_cur[NMAX];
__device__ int   g_src[ETOTAL];
__device__ int   g_bsum[NSCAN + 1];

// ---------------- CSR build ----------------
__global__ void zero_deg_kernel(int n) {
    int i = blockIdx.x * blockDim.x + threadIdx.x;
    if (i <= n) g_deg[i] = 0;
}

__global__ void hist_kernel(const int* __restrict__ ei, int E, int n) {
    int e = blockIdx.x * blockDim.x + threadIdx.x;
    int tot = E + n;
    if (e < tot) {
        int d = (e < E) ? ei[E + e] : (e - E);
        if (d < 0) d = 0;
        if (d >= n) d = n - 1;
        atomicAdd(&g_deg[d], 1);
    }
}

__global__ void scan1_kernel(int n) {
    __shared__ int sh[SCAN_BLK];
    int tid = threadIdx.x;
    int idx = blockIdx.x * SCAN_BLK + tid;
    int v = (idx < n) ? g_deg[idx] : 0;
    sh[tid] = v;
    __syncthreads();
    for (int d = 1; d < SCAN_BLK; d <<= 1) {
        int t = sh[tid];
        int add = (tid >= d) ? sh[tid - d] : 0;
        __syncthreads();
        sh[tid] = t + add;
        __syncthreads();
    }
    if (idx < n) g_off[idx] = sh[tid] - v;
    if (tid == SCAN_BLK - 1) g_bsum[blockIdx.x] = sh[tid];
}

__global__ void scan2_kernel(int nb, int n) {
    __shared__ int wsum[2];
    int t = threadIdx.x;
    int w = t >> 5, l = t & 31;
    int v = (t < nb) ? g_bsum[t] : 0;
    int sc = v;
#pragma unroll
    for (int d = 1; d < 32; d <<= 1) {
        int u = __shfl_up_sync(0xffffffffu, sc, d);
        if (l >= d) sc += u;
    }
    if (l == 31) wsum[w] = sc;
    __syncthreads();
    int base = (w == 1) ? wsum[0] : 0;
    if (t < nb) g_bsum[t] = sc - v + base;
    if (t == 0) {
        int tot = wsum[0] + ((nb > 32) ? wsum[1] : 0);
        if (nb <= 32) tot = wsum[0];
        g_off[n] = tot;
    }
}

__global__ void scan3_kernel(int n) {
    int idx = blockIdx.x * SCAN_BLK + threadIdx.x;
    if (idx < n) {
        int o = g_off[idx] + g_bsum[blockIdx.x];
        g_off[idx] = o;
        g_cur[idx] = o;
    }
}

__global__ void scatter_kernel(const int* __restrict__ ei, int E, int n) {
    int e = blockIdx.x * blockDim.x + threadIdx.x;
    int tot = E + n;
    if (e < tot) {
        int s, d;
        if (e < E) { s = ei[e]; d = ei[E + e]; }
        else       { s = d = e - E; }
        if (s < 0) s = 0; if (s >= n) s = n - 1;
        if (d < 0) d = 0; if (d >= n) d = n - 1;
        int pos = atomicAdd(&g_cur[d], 1);
        if (pos >= 0 && pos < ETOTAL) g_src[pos] = s;
    }
}

// ---------------- fp32 -> fp16 convert ----------------
__global__ void conv_h_kernel(const float* __restrict__ in, __half* __restrict__ out, int n4) {
    int i = blockIdx.x * blockDim.x + threadIdx.x;
    if (i < n4) {
        float4 v = ((const float4*)in)[i];
        __half2 h0 = __floats2half2_rn(v.x, v.y);
        __half2 h1 = __floats2half2_rn(v.z, v.w);
        ((__half2*)out)[2 * i] = h0;
        ((__half2*)out)[2 * i + 1] = h1;
    }
}

// ---------------- pack Wl|Wr -> Bt[n][k] (transposed), fp16 ----------
__global__ void pack_bt_h_kernel(const float* __restrict__ Wl, const float* __restrict__ Wr,
                                 __half* __restrict__ bh, int K, int Nhalf) {
    int idx = blockIdx.x * blockDim.x + threadIdx.x;
    int tot = 2 * Nhalf * K;
    if (idx < tot) {
        int n = idx / K, k = idx % K;
        float v = (n < Nhalf) ? Wl[(size_t)k * Nhalf + n] : Wr[(size_t)k * Nhalf + (n - Nhalf)];
        bh[idx] = __float2half_rn(v);
    }
}

// ---------------- async copy + ldmatrix + mma helpers ----------------
__device__ __forceinline__ void cp16(void* sdst, const void* gsrc, int src_bytes) {
    uint32_t s = (uint32_t)__cvta_generic_to_shared(sdst);
    asm volatile("cp.async.cg.shared.global [%0], [%1], 16, %2;\n"
                 :: "r"(s), "l"(gsrc), "r"(src_bytes));
}
__device__ __forceinline__ void cp_commit() { asm volatile("cp.async.commit_group;\n"); }
__device__ __forceinline__ void cp_wait1() { asm volatile("cp.async.wait_group 1;\n"); }
__device__ __forceinline__ void cp_wait0() { asm volatile("cp.async.wait_group 0;\n"); }

__device__ __forceinline__ void ldsm4(uint32_t r[4], const void* p) {
    uint32_t a = (uint32_t)__cvta_generic_to_shared(p);
    asm volatile("ldmatrix.sync.aligned.m8n8.x4.shared.b16 {%0,%1,%2,%3}, [%4];\n"
                 : "=r"(r[0]), "=r"(r[1]), "=r"(r[2]), "=r"(r[3]) : "r"(a));
}

__device__ __forceinline__ void mma_f16(float d[4], const uint32_t a[4], const uint32_t b[2]) {
    asm volatile(
        "mma.sync.aligned.m16n8k16.row.col.f32.f16.f16.f32 "
        "{%0,%1,%2,%3}, {%4,%5,%6,%7}, {%8,%9}, {%0,%1,%2,%3};\n"
        : "+f"(d[0]), "+f"(d[1]), "+f"(d[2]), "+f"(d[3])
        : "r"(a[0]), "r"(a[1]), "r"(a[2]), "r"(a[3]), "r"(b[0]), "r"(b[1]));
}

// ---- fp16 GEMM, 32-wide K stages (2 chunks per sync), both outputs fp16 ----
// C[M, Ntot] = A[M,K] x Bt[Ntot,K]^T; cols < ncut -> H0, else H1 (both ld = ld).
template <int KCHUNKS>
__global__ __launch_bounds__(256, 2)
void hgemm_kernel(const __half* __restrict__ A, const __half* __restrict__ Bt,
                  __half* __restrict__ H0, __half* __restrict__ H1,
                  int M, int ncut, int ld) {
    constexpr int K = KCHUNKS * 16;
    constexpr int S = KCHUNKS / 2;           // 32-wide stages
    extern __shared__ __half sm[];

    int t = threadIdx.x;
    int lane = t & 31, wid = t >> 5;
    int wm = wid & 1, wn = wid >> 1;          // 2 x 4 warp grid
    int group = lane >> 2, tig = lane & 3;
    int m0 = blockIdx.y * 128, n0 = blockIdx.x * 128;

    int a_row = lane & 15;
    int a_col = ((lane >> 4) & 1) * 8;
    int b_row = ((lane >> 4) & 1) * 8 + (lane & 7);
    int b_col = ((lane >> 3) & 1) * 8;

    float acc[4][4][4];
#pragma unroll
    for (int i = 0; i < 4; i++)
#pragma unroll
        for (int j = 0; j < 4; j++)
#pragma unroll
            for (int q = 0; q < 4; q++) acc[i][j][q] = 0.f;

    int lrow = t >> 1, lkq = (t & 1) * 8;
    int grow = m0 + lrow;
    int abytes = (grow < M) ? 16 : 0;
    const __half* pA = A + (size_t)(grow < M ? grow : 0) * K + lkq;
    const __half* pB = Bt + (size_t)(n0 + lrow) * K + lkq;
    int lofs = lrow * 24 + lkq;

    // stage: A c0 | A c1 | B c0 | B c1, each [128][24]
    auto load_stage = [&](int s, int ring) {
        __half* base = sm + ring * HG_STAGE_ELEMS;
        int k0 = s * 32;
        cp16(base + lofs,        pA + k0, abytes);
        cp16(base + 3072 + lofs, pA + k0 + 16, abytes);
        cp16(base + 6144 + lofs, pB + k0, 16);
        cp16(base + 9216 + lofs, pB + k0 + 16, 16);
        cp_commit();
    };

    load_stage(0, 0);
    if (S > 1) load_stage(1, 1);

#pragma unroll
    for (int s = 0; s < S; s++) {
        if (s + 1 < S) cp_wait1(); else cp_wait0();
        __syncthreads();
        if (s + 2 < S) load_stage(s + 2, (s + 2) % 3);

        __half* base = sm + (s % 3) * HG_STAGE_ELEMS;
#pragma unroll
        for (int cc = 0; cc < 2; cc++) {
            __half* as = base + cc * 3072;
            __half* bs = base + 6144 + cc * 3072;

            uint32_t af[4][4];
#pragma unroll
            for (int mf = 0; mf < 4; mf++) {
                int r0 = wm * 64 + mf * 16;
                ldsm4(af[mf], as + (r0 + a_row) * 24 + a_col);
            }
            uint32_t bf[2][4];
#pragma unroll
            for (int p = 0; p < 2; p++) {
                int c0 = wn * 32 + p * 16;
                ldsm4(bf[p], bs + (c0 + b_row) * 24 + b_col);
            }
#pragma unroll
            for (int nf = 0; nf < 4; nf++) {
                const uint32_t* bp = &bf[nf >> 1][(nf & 1) * 2];
#pragma unroll
                for (int mf = 0; mf < 4; mf++)
                    mma_f16(acc[mf][nf], af[mf], bp);
            }
        }
    }

#pragma unroll
    for (int mf = 0; mf < 4; mf++) {
        int r = m0 + wm * 64 + mf * 16 + group;
#pragma unroll
        for (int nf = 0; nf < 4; nf++) {
            int cc = n0 + wn * 32 + nf * 8 + tig * 2;
            __half* dst = H0;
            int ccol = cc;
            if (cc >= ncut) { dst = H1; ccol = cc - ncut; }
            if (r < M)
                *(__half2*)&dst[(size_t)r * ld + ccol] =
                    __floats2half2_rn(acc[mf][nf][0], acc[mf][nf][1]);
            if (r + 8 < M)
                *(__half2*)&dst[(size_t)(r + 8) * ld + ccol] =
                    __floats2half2_rn(acc[mf][nf][2], acc[mf][nf][3]);
        }
    }
}

#define LRELU(v) ((v) > 0.f ? (v) : 0.2f * (v))

// unpack 8 halves (uint4) to 8 floats
__device__ __forceinline__ void h8_to_f8(uint4 raw, float f[8]) {
    float2 p0 = __half22float2(*(__half2*)&raw.x);
    float2 p1 = __half22float2(*(__half2*)&raw.y);
    float2 p2 = __half22float2(*(__half2*)&raw.z);
    float2 p3 = __half22float2(*(__half2*)&raw.w);
    f[0] = p0.x; f[1] = p0.y; f[2] = p1.x; f[3] = p1.y;
    f[4] = p2.x; f[5] = p2.y; f[6] = p3.x; f[7] = p3.y;
}

// ---------------- Layer 1 GAT (fp16 xl/xr, 8 edges in flight) --------------
__global__ void gat1_kernel(const float* __restrict__ att1, const float* __restrict__ b1,
                            const float* __restrict__ lng, const float* __restrict__ lnb,
                            int Nn) {
    int i = blockIdx.x;
    int t = threadIdx.x;
    int h = t >> 5;
    int l = t & 31;
    int s = l >> 3;
    int c = l & 7;
    __shared__ float sout[256];
    __shared__ float red[4];
    __shared__ float red2[4];

    uint4 xr_raw = *(const uint4*)(g_xrh + (size_t)i * 256 + h * 64 + c * 8);
    float xr[8];
    h8_to_f8(xr_raw, xr);
    const float* atp = att1 + h * 64 + c * 8;
    float4 at0 = ((const float4*)atp)[0];
    float4 at1 = ((const float4*)atp)[1];
    float at[8] = {at0.x, at0.y, at0.z, at0.w, at1.x, at1.y, at1.z, at1.w};

    float acc[8] = {0.f, 0.f, 0.f, 0.f, 0.f, 0.f, 0.f, 0.f};
    float den = 0.f;
    int e0 = g_off[i], deg = g_off[i + 1] - e0;
    for (int base = 0; base < deg; base += 8) {
        int v0 = (base + s) < deg;
        int v1 = (base + 4 + s) < deg;
        int j0 = v0 ? __ldg(&g_src[e0 + base + s]) : 0;
        int j1 = v1 ? __ldg(&g_src[e0 + base + 4 + s]) : 0;
        uint4 r0 = *(const uint4*)(g_xlh + (size_t)j0 * 256 + h * 64 + c * 8);
        uint4 r1 = *(const uint4*)(g_xlh + (size_t)j1 * 256 + h * 64 + c * 8);
        float xa[8], xb[8];
        h8_to_f8(r0, xa);
        h8_to_f8(r1, xb);
        float ta = 0.f, tb = 0.f;
#pragma unroll
        for (int k = 0; k < 8; k++) {
            ta += LRELU(xa[k] + xr[k]) * at[k];
            tb += LRELU(xb[k] + xr[k]) * at[k];
        }
#pragma unroll
        for (int o = 1; o <= 4; o <<= 1) {
            ta += __shfl_xor_sync(0xffffffffu, ta, o);
            tb += __shfl_xor_sync(0xffffffffu, tb, o);
        }
        float a0 = v0 ? __expf(ta) : 0.f;
        float a1 = v1 ? __expf(tb) : 0.f;
#pragma unroll
        for (int k = 0; k < 8; k++) acc[k] += a0 * xa[k] + a1 * xb[k];
        den += a0 + a1;
    }
#pragma unroll
    for (int k = 0; k < 8; k++) {
        acc[k] += __shfl_xor_sync(0xffffffffu, acc[k], 8);
        acc[k] += __shfl_xor_sync(0xffffffffu, acc[k], 16);
    }
    den += __shfl_xor_sync(0xffffffffu, den, 8);
    den += __shfl_xor_sync(0xffffffffu, den, 16);
    float inv = 1.f / (den + 1e-16f);
    if (s == 0) {
#pragma unroll
        for (int k = 0; k < 8; k++) sout[h * 64 + c * 8 + k] = acc[k] * inv;
    }
    __syncthreads();

    int w = t >> 5, lane = t & 31;
    float val = 0.f;
    if (t < 64)
        val = 0.25f * (sout[t] + sout[t + 64] + sout[t + 128] + sout[t + 192]) + b1[t];

    float v = (t < 64) ? val : 0.f;
#pragma unroll
    for (int o = 16; o; o >>= 1) v += __shfl_xor_sync(0xffffffffu, v, o);
    if (lane == 0) red[w] = v;
    __syncthreads();
    float mu = (red[0] + red[1] + red[2] + red[3]) * (1.f / 64.f);
    float dd = (t < 64) ? (val - mu) : 0.f;
    float v2 = dd * dd;
#pragma unroll
    for (int o = 16; o; o >>= 1) v2 += __shfl_xor_sync(0xffffffffu, v2, o);
    if (lane == 0) red2[w] = v2;
    __syncthreads();
    float var = (red2[0] + red2[1] + red2[2] + red2[3]) * (1.f / 64.f);
    if (t < 64) {
        float y = dd * rsqrtf(var + 1e-5f) * lng[t] + lnb[t];
        float hv = fmaxf(y, 0.f);
        g_ah[(size_t)i * HID + t] = __float2half_rn(hv);
    }
}

// ---------------- Layer 2 GAT: fp16 xl2/xr2 (ld 64), 8 edges in flight -----
__global__ void gat2_kernel(const float* __restrict__ att2, const float* __restrict__ b2,
                            const float* __restrict__ lng, const float* __restrict__ lnb,
                            float* __restrict__ out, int Nn) {
    int w = threadIdx.x >> 5, l = threadIdx.x & 31;
    int i = blockIdx.x * 4 + w;
    if (i >= Nn) return;
    int s = l >> 3;
    int c = l & 7;

    uint4 xr_raw = *(const uint4*)(g_xrh + (size_t)i * OUTD + c * 8);
    float xr[8];
    h8_to_f8(xr_raw, xr);
    const float* atp = att2 + c * 8;
    float4 at0 = ((const float4*)atp)[0];
    float4 at1 = ((const float4*)atp)[1];
    float at[8] = {at0.x, at0.y, at0.z, at0.w, at1.x, at1.y, at1.z, at1.w};

    float acc[8] = {0.f, 0.f, 0.f, 0.f, 0.f, 0.f, 0.f, 0.f};
    float den = 0.f;
    int e0 = g_off[i], deg = g_off[i + 1] - e0;
    for (int base = 0; base < deg; base += 8) {
        int v0 = (base + s) < deg;
        int v1 = (base + 4 + s) < deg;
        int j0 = v0 ? __ldg(&g_src[e0 + base + s]) : 0;
        int j1 = v1 ? __ldg(&g_src[e0 + base + 4 + s]) : 0;
        uint4 r0 = *(const uint4*)(g_xlh + (size_t)j0 * OUTD + c * 8);
        uint4 r1 = *(const uint4*)(g_xlh + (size_t)j1 * OUTD + c * 8);
        float xa[8], xb[8];
        h8_to_f8(r0, xa);
        h8_to_f8(r1, xb);
        float ta = 0.f, tb = 0.f;
#pragma unroll
        for (int k = 0; k < 8; k++) {
            ta += LRELU(xa[k] + xr[k]) * at[k];
            tb += LRELU(xb[k] + xr[k]) * at[k];
        }
#pragma unroll
        for (int o = 1; o <= 4; o <<= 1) {
            ta += __shfl_xor_sync(0xffffffffu, ta, o);
            tb += __shfl_xor_sync(0xffffffffu, tb, o);
        }
        float a0 = v0 ? __expf(ta) : 0.f;
        float a1 = v1 ? __expf(tb) : 0.f;
#pragma unroll
        for (int k = 0; k < 8; k++) acc[k] += a0 * xa[k] + a1 * xb[k];
        den += a0 + a1;
    }
#pragma unroll
    for (int k = 0; k < 8; k++) {
        acc[k] += __shfl_xor_sync(0xffffffffu, acc[k], 8);
        acc[k] += __shfl_xor_sync(0xffffffffu, acc[k], 16);
    }
    den += __shfl_xor_sync(0xffffffffu, den, 8);
    den += __shfl_xor_sync(0xffffffffu, den, 16);
    float inv = 1.f / (den + 1e-16f);

    const float* bp = b2 + c * 8;
    float4 bb0 = ((const float4*)bp)[0];
    float4 bb1 = ((const float4*)bp)[1];
    float bb[8] = {bb0.x, bb0.y, bb0.z, bb0.w, bb1.x, bb1.y, bb1.z, bb1.w};
    float v[8];
#pragma unroll
    for (int k = 0; k < 8; k++) v[k] = acc[k] * inv + bb[k];

    float sum = v[0] + v[1] + v[2] + v[3] + v[4] + v[5] + v[6] + v[7];
#pragma unroll
    for (int o = 16; o; o >>= 1) sum += __shfl_xor_sync(0xffffffffu, sum, o);
    float mu = sum * (1.f / 256.f);
    float q = 0.f;
    float d[8];
#pragma unroll
    for (int k = 0; k < 8; k++) { d[k] = v[k] - mu; q += d[k] * d[k]; }
#pragma unroll
    for (int o = 16; o; o >>= 1) q += __shfl_xor_sync(0xffffffffu, q, o);
    float var = q * (1.f / 256.f);
    float r = rsqrtf(var + 1e-5f);
    if (s == 0) {
        const float* gp = lng + c * 8;
        const float* np = lnb + c * 8;
        float4 gg0 = ((const float4*)gp)[0], gg1 = ((const float4*)gp)[1];
        float4 nn0 = ((const float4*)np)[0], nn1 = ((const float4*)np)[1];
        float4 o0, o1;
        o0.x = d[0] * r * gg0.x + nn0.x; o0.y = d[1] * r * gg0.y + nn0.y;
        o0.z = d[2] * r * gg0.z + nn0.z; o0.w = d[3] * r * gg0.w + nn0.w;
        o1.x = d[4] * r * gg1.x + nn1.x; o1.y = d[5] * r * gg1.y + nn1.y;
        o1.z = d[6] * r * gg1.z + nn1.z; o1.w = d[7] * r * gg1.w + nn1.w;
        float* op = out + (size_t)i * OUTD + c * 8;
        ((float4*)op)[0] = o0;
        ((float4*)op)[1] = o1;
    }
}

// ---------------- launch ----------------
extern "C" void kernel_launch(void* const* d_in, const int* in_sizes, int n_in,
                              void* d_out, int out_size) {
    const float* x    = (const float*)d_in[0];
    const int*   ei   = (const int*)d_in[1];
    const float* W1l  = (const float*)d_in[2];
    const float* W1r  = (const float*)d_in[3];
    const float* att1 = (const float*)d_in[4];
    const float* b1   = (const float*)d_in[5];
    const float* ln1g = (const float*)d_in[6];
    const float* ln1b = (const float*)d_in[7];
    const float* W2l  = (const float*)d_in[8];
    const float* W2r  = (const float*)d_in[9];
    const float* att2 = (const float*)d_in[10];
    const float* b2   = (const float*)d_in[11];
    const float* ln2g = (const float*)d_in[12];
    const float* ln2b = (const float*)d_in[13];
    float* out = (float*)d_out;

    int N = in_sizes[0] / IN_DIM;
    int E = in_sizes[1] / 2;
    if (N > NMAX) N = NMAX;
    if (E > EMAX) E = EMAX;
    int ETOT_RT = E + N;
    int nscan = (N + SCAN_BLK - 1) / SCAN_BLK;

    __half *p_xrh, *p_xlh, *p_ah, *p_bh, *p_bh2;
    cudaGetSymbolAddress((void**)&p_xrh, g_xrh);
    cudaGetSymbolAddress((void**)&p_xlh, g_xlh);
    cudaGetSymbolAddress((void**)&p_ah,  g_ah);
    cudaGetSymbolAddress((void**)&p_bh,  g_bh);
    cudaGetSymbolAddress((void**)&p_bh2, g_bh2);

    cudaFuncSetAttribute(hgemm_kernel<16>, cudaFuncAttributeMaxDynamicSharedMemorySize, HG_SMEM_BYTES);
    cudaFuncSetAttribute(hgemm_kernel<4>,  cudaFuncAttributeMaxDynamicSharedMemorySize, HG_SMEM_BYTES);

    static cudaStream_t s2 = nullptr;
    static cudaEvent_t ev_fork = nullptr, ev_g1 = nullptr;
    if (!s2) {
        cudaStreamCreateWithFlags(&s2, cudaStreamNonBlocking);
        cudaEventCreateWithFlags(&ev_fork, cudaEventDisableTiming);
        cudaEventCreateWithFlags(&ev_g1, cudaEventDisableTiming);
    }

    cudaEventRecord(ev_fork, 0);
    cudaStreamWaitEvent(s2, ev_fork, 0);

    // ---- stream s2: layer-1 GEMM chain (fp16 in, fp16 out xl/xr) ----
    {
        int n4 = N * IN_DIM / 4;
        conv_h_kernel<<<(n4 + 255) / 256, 256, 0, s2>>>(x, p_ah, n4);
        pack_bt_h_kernel<<<(512 * 256 + 255) / 256, 256, 0, s2>>>(W1l, W1r, p_bh, 256, 256);
        pack_bt_h_kernel<<<(128 * 64 + 255) / 256, 256, 0, s2>>>(W2l, W2r, p_bh2, 64, 64);
        dim3 grid(4, (N + 127) / 128);
        hgemm_kernel<16><<<grid, 256, HG_SMEM_BYTES, s2>>>(p_ah, p_bh, p_xlh, p_xrh, N, 256, 256);
        cudaEventRecord(ev_g1, s2);
    }

    // ---- default stream: CSR build (concurrent) ----
    zero_deg_kernel<<<(N + 256) / 256, 256>>>(N);
    hist_kernel<<<(ETOT_RT + 255) / 256, 256>>>(ei, E, N);
    scan1_kernel<<<nscan, SCAN_BLK>>>(N);
    scan2_kernel<<<1, 64>>>(nscan, N);
    scan3_kernel<<<nscan, SCAN_BLK>>>(N);
    scatter_kernel<<<(ETOT_RT + 255) / 256, 256>>>(ei, E, N);

    cudaStreamWaitEvent(0, ev_g1, 0);

    gat1_kernel<<<N, 128>>>(att1, b1, ln1g, ln1b, N);

    // Layer 2 GEMM: xl2 -> g_xlh (ld 64), xr2 -> g_xrh (ld 64)
    {
        dim3 grid(1, (N + 127) / 128);
        hgemm_kernel<4><<<grid, 256, HG_SMEM_BYTES>>>(p_ah, p_bh2, p_xlh, p_xrh, N, 64, 64);
    }

    gat2_kernel<<<(N + 3) / 4, 128>>>(att2, b2, ln2g, ln2b, out, N);
}

// round 15
// speedup vs baseline: 1.5408x; 1.5408x over previous
#include <cuda_runtime.h>
#include <cuda_bf16.h>
#include <cuda_fp16.h>
#include <math.h>
#include <stdint.h>

#define NMAX 50000
#define EMAX 800000
#define ETOTAL (EMAX + NMAX)
#define IN_DIM 256
#define HID 64
#define L1C 256
#define OUTD 64
#define SCAN_BLK 1024
#define NSCAN ((NMAX + SCAN_BLK - 1) / SCAN_BLK)

// fp16 GEMM: 3 stages x 2 arrays x [128][24] half
#define HG_STAGE_ELEMS (2 * 128 * 24)
#define HG_SMEM_BYTES (3 * HG_STAGE_ELEMS * 2)

// ---------------- scratch (device globals; allocation-free) ----------------
__device__ float  g_xr1[(size_t)NMAX * L1C];  // layer1 xr fp32; reused for layer2 xr2
__device__ __half g_xlh[(size_t)NMAX * 256];  // layer1 xl fp16 (ld 256); layer2 xl2 (ld 64)
__device__ __half g_ah[(size_t)NMAX * 256];   // fp16 A (x, then h)
__device__ __half g_bh[512 * 256];            // packed W1 transposed fp16
__device__ __half g_bh2[128 * 64];            // packed W2 transposed fp16
__device__ int   g_deg[NMAX + 1];
__device__ int   g_off[NMAX + 1];
__device__ int   g_cur[NMAX];
__device__ int   g_src[ETOTAL];
__device__ int   g_bsum[NSCAN + 1];

// ---------------- CSR build ----------------
__global__ void zero_deg_kernel(int n) {
    int i = blockIdx.x * blockDim.x + threadIdx.x;
    if (i <= n) g_deg[i] = 0;
}

__global__ void hist_kernel(const int* __restrict__ ei, int E, int n) {
    int e = blockIdx.x * blockDim.x + threadIdx.x;
    int tot = E + n;
    if (e < tot) {
        int d = (e < E) ? ei[E + e] : (e - E);
        if (d < 0) d = 0;
        if (d >= n) d = n - 1;
        atomicAdd(&g_deg[d], 1);
    }
}

__global__ void scan1_kernel(int n) {
    __shared__ int sh[SCAN_BLK];
    int tid = threadIdx.x;
    int idx = blockIdx.x * SCAN_BLK + tid;
    int v = (idx < n) ? g_deg[idx] : 0;
    sh[tid] = v;
    __syncthreads();
    for (int d = 1; d < SCAN_BLK; d <<= 1) {
        int t = sh[tid];
        int add = (tid >= d) ? sh[tid - d] : 0;
        __syncthreads();
        sh[tid] = t + add;
        __syncthreads();
    }
    if (idx < n) g_off[idx] = sh[tid] - v;
    if (tid == SCAN_BLK - 1) g_bsum[blockIdx.x] = sh[tid];
}

__global__ void scan2_kernel(int nb, int n) {
    __shared__ int wsum[2];
    int t = threadIdx.x;
    int w = t >> 5, l = t & 31;
    int v = (t < nb) ? g_bsum[t] : 0;
    int sc = v;
#pragma unroll
    for (int d = 1; d < 32; d <<= 1) {
        int u = __shfl_up_sync(0xffffffffu, sc, d);
        if (l >= d) sc += u;
    }
    if (l == 31) wsum[w] = sc;
    __syncthreads();
    int base = (w == 1) ? wsum[0] : 0;
    if (t < nb) g_bsum[t] = sc - v + base;
    if (t == 0) {
        int tot = wsum[0] + ((nb > 32) ? wsum[1] : 0);
        if (nb <= 32) tot = wsum[0];
        g_off[n] = tot;
    }
}

__global__ void scan3_kernel(int n) {
    int idx = blockIdx.x * SCAN_BLK + threadIdx.x;
    if (idx < n) {
        int o = g_off[idx] + g_bsum[blockIdx.x];
        g_off[idx] = o;
        g_cur[idx] = o;
    }
}

__global__ void scatter_kernel(const int* __restrict__ ei, int E, int n) {
    int e = blockIdx.x * blockDim.x + threadIdx.x;
    int tot = E + n;
    if (e < tot) {
        int s, d;
        if (e < E) { s = ei[e]; d = ei[E + e]; }
        else       { s = d = e - E; }
        if (s < 0) s = 0; if (s >= n) s = n - 1;
        if (d < 0) d = 0; if (d >= n) d = n - 1;
        int pos = atomicAdd(&g_cur[d], 1);
        if (pos >= 0 && pos < ETOTAL) g_src[pos] = s;
    }
}

// ---------------- fp32 -> fp16 convert ----------------
__global__ void conv_h_kernel(const float* __restrict__ in, __half* __restrict__ out, int n4) {
    int i = blockIdx.x * blockDim.x + threadIdx.x;
    if (i < n4) {
        float4 v = ((const float4*)in)[i];
        __half2 h0 = __floats2half2_rn(v.x, v.y);
        __half2 h1 = __floats2half2_rn(v.z, v.w);
        ((__half2*)out)[2 * i] = h0;
        ((__half2*)out)[2 * i + 1] = h1;
    }
}

// ---------------- pack Wl|Wr -> Bt[n][k] (transposed), fp16 ----------
__global__ void pack_bt_h_kernel(const float* __restrict__ Wl, const float* __restrict__ Wr,
                                 __half* __restrict__ bh, int K, int Nhalf) {
    int idx = blockIdx.x * blockDim.x + threadIdx.x;
    int tot = 2 * Nhalf * K;
    if (idx < tot) {
        int n = idx / K, k = idx % K;
        float v = (n < Nhalf) ? Wl[(size_t)k * Nhalf + n] : Wr[(size_t)k * Nhalf + (n - Nhalf)];
        bh[idx] = __float2half_rn(v);
    }
}

// ---------------- async copy + ldmatrix + mma helpers ----------------
__device__ __forceinline__ void cp16(void* sdst, const void* gsrc, int src_bytes) {
    uint32_t s = (uint32_t)__cvta_generic_to_shared(sdst);
    asm volatile("cp.async.cg.shared.global [%0], [%1], 16, %2;\n"
                 :: "r"(s), "l"(gsrc), "r"(src_bytes));
}
__device__ __forceinline__ void cp_commit() { asm volatile("cp.async.commit_group;\n"); }
__device__ __forceinline__ void cp_wait1() { asm volatile("cp.async.wait_group 1;\n"); }
__device__ __forceinline__ void cp_wait0() { asm volatile("cp.async.wait_group 0;\n"); }

__device__ __forceinline__ void ldsm4(uint32_t r[4], const void* p) {
    uint32_t a = (uint32_t)__cvta_generic_to_shared(p);
    asm volatile("ldmatrix.sync.aligned.m8n8.x4.shared.b16 {%0,%1,%2,%3}, [%4];\n"
                 : "=r"(r[0]), "=r"(r[1]), "=r"(r[2]), "=r"(r[3]) : "r"(a));
}

__device__ __forceinline__ void mma_f16(float d[4], const uint32_t a[4], const uint32_t b[2]) {
    asm volatile(
        "mma.sync.aligned.m16n8k16.row.col.f32.f16.f16.f32 "
        "{%0,%1,%2,%3}, {%4,%5,%6,%7}, {%8,%9}, {%0,%1,%2,%3};\n"
        : "+f"(d[0]), "+f"(d[1]), "+f"(d[2]), "+f"(d[3])
        : "r"(a[0]), "r"(a[1]), "r"(a[2]), "r"(a[3]), "r"(b[0]), "r"(b[1]));
}

// ---- fp16 tensor-core GEMM; cols < ncut -> H0 (fp16), else C1 (fp32) ----
template <int KCHUNKS>
__global__ __launch_bounds__(256, 2)
void hgemm_kernel(const __half* __restrict__ A, const __half* __restrict__ Bt,
                  __half* __restrict__ H0, float* __restrict__ C1,
                  int M, int ncut, int ld) {
    constexpr int K = KCHUNKS * 16;
    extern __shared__ __half sm[];
    __half* stage_base[3] = { sm, sm + HG_STAGE_ELEMS, sm + 2 * HG_STAGE_ELEMS };

    int t = threadIdx.x;
    int lane = t & 31, wid = t >> 5;
    int wm = wid & 1, wn = wid >> 1;          // 2 x 4 warp grid
    int group = lane >> 2, tig = lane & 3;
    int m0 = blockIdx.y * 128, n0 = blockIdx.x * 128;

    int a_row = lane & 15;
    int a_col = ((lane >> 4) & 1) * 8;
    int b_row = ((lane >> 4) & 1) * 8 + (lane & 7);
    int b_col = ((lane >> 3) & 1) * 8;

    float acc[4][4][4];
#pragma unroll
    for (int i = 0; i < 4; i++)
#pragma unroll
        for (int j = 0; j < 4; j++)
#pragma unroll
            for (int q = 0; q < 4; q++) acc[i][j][q] = 0.f;

    int lrow = t >> 1, lkq = (t & 1) * 8;
    int grow = m0 + lrow;
    int abytes = (grow < M) ? 16 : 0;
    const __half* pA = A + (size_t)(grow < M ? grow : 0) * K + lkq;
    const __half* pB = Bt + (size_t)(n0 + lrow) * K + lkq;
    int lofs = lrow * 24 + lkq;

    auto load_stage = [&](int c, int st) {
        __half* base = stage_base[st];
        int ko = c * 16;
        cp16(base + lofs,        pA + ko, abytes);
        cp16(base + 3072 + lofs, pB + ko, 16);
        cp_commit();
    };

    load_stage(0, 0);
    if (KCHUNKS > 1) load_stage(1, 1);

#pragma unroll
    for (int c = 0; c < KCHUNKS; c++) {
        if (c + 1 < KCHUNKS) cp_wait1(); else cp_wait0();
        __syncthreads();
        if (c + 2 < KCHUNKS) load_stage(c + 2, (c + 2) % 3);

        __half* base = stage_base[c % 3];
        __half* as = base;
        __half* bs = base + 3072;

        uint32_t af[4][4];
#pragma unroll
        for (int mf = 0; mf < 4; mf++) {
            int r0 = wm * 64 + mf * 16;
            ldsm4(af[mf], as + (r0 + a_row) * 24 + a_col);
        }
        uint32_t bf[2][4];
#pragma unroll
        for (int p = 0; p < 2; p++) {
            int c0 = wn * 32 + p * 16;
            ldsm4(bf[p], bs + (c0 + b_row) * 24 + b_col);
        }
#pragma unroll
        for (int nf = 0; nf < 4; nf++) {
            const uint32_t* bp = &bf[nf >> 1][(nf & 1) * 2];
#pragma unroll
            for (int mf = 0; mf < 4; mf++)
                mma_f16(acc[mf][nf], af[mf], bp);
        }
    }

#pragma unroll
    for (int mf = 0; mf < 4; mf++) {
        int r = m0 + wm * 64 + mf * 16 + group;
#pragma unroll
        for (int nf = 0; nf < 4; nf++) {
            int cc = n0 + wn * 32 + nf * 8 + tig * 2;
            if (cc < ncut) {
                if (r < M)
                    *(__half2*)&H0[(size_t)r * ld + cc] =
                        __floats2half2_rn(acc[mf][nf][0], acc[mf][nf][1]);
                if (r + 8 < M)
                    *(__half2*)&H0[(size_t)(r + 8) * ld + cc] =
                        __floats2half2_rn(acc[mf][nf][2], acc[mf][nf][3]);
            } else {
                int ccol = cc - ncut;
                if (r < M)
                    *(float2*)&C1[(size_t)r * ld + ccol] = make_float2(acc[mf][nf][0], acc[mf][nf][1]);
                if (r + 8 < M)
                    *(float2*)&C1[(size_t)(r + 8) * ld + ccol] = make_float2(acc[mf][nf][2], acc[mf][nf][3]);
            }
        }
    }
}

#define LRELU(v) ((v) > 0.f ? (v) : 0.2f * (v))

// unpack 8 halves (uint4) to 8 floats
__device__ __forceinline__ void h8_to_f8(uint4 raw, float f[8]) {
    float2 p0 = __half22float2(*(__half2*)&raw.x);
    float2 p1 = __half22float2(*(__half2*)&raw.y);
    float2 p2 = __half22float2(*(__half2*)&raw.z);
    float2 p3 = __half22float2(*(__half2*)&raw.w);
    f[0] = p0.x; f[1] = p0.y; f[2] = p1.x; f[3] = p1.y;
    f[4] = p2.x; f[5] = p2.y; f[6] = p3.x; f[7] = p3.y;
}

// ---------------- Layer 1 GAT (xl fp16, pipelined gather) ------------------
__global__ void gat1_kernel(const float* __restrict__ att1, const float* __restrict__ b1,
                            const float* __restrict__ lng, const float* __restrict__ lnb,
                            int Nn) {
    int i = blockIdx.x;
    int t = threadIdx.x;
    int h = t >> 5;
    int l = t & 31;
    int s = l >> 3;
    int c = l & 7;
    __shared__ float sout[256];
    __shared__ float red[4];
    __shared__ float red2[4];

    const float* xrp = g_xr1 + (size_t)i * L1C + h * 64 + c * 8;
    float4 xr0 = ((const float4*)xrp)[0];
    float4 xr1 = ((const float4*)xrp)[1];
    const float* atp = att1 + h * 64 + c * 8;
    float4 at0 = ((const float4*)atp)[0];
    float4 at1 = ((const float4*)atp)[1];
    float xr[8] = {xr0.x, xr0.y, xr0.z, xr0.w, xr1.x, xr1.y, xr1.z, xr1.w};
    float at[8] = {at0.x, at0.y, at0.z, at0.w, at1.x, at1.y, at1.z, at1.w};

    float acc[8] = {0.f, 0.f, 0.f, 0.f, 0.f, 0.f, 0.f, 0.f};
    float den = 0.f;
    int e0 = g_off[i], deg = g_off[i + 1] - e0;

    // 2-deep software pipeline: gather for iter n+1 is issued before iter n's math
    int v_cur = s < deg;
    int j_cur = v_cur ? __ldg(&g_src[e0 + s]) : 0;
    uint4 r_cur = *(const uint4*)(g_xlh + (size_t)j_cur * 256 + h * 64 + c * 8);
    for (int base = 0; base < deg; base += 4) {
        int nb = base + 4;
        int v_nxt = (nb + s) < deg;
        int j_nxt = v_nxt ? __ldg(&g_src[e0 + nb + s]) : 0;
        uint4 r_nxt = *(const uint4*)(g_xlh + (size_t)j_nxt * 256 + h * 64 + c * 8);

        float xa[8];
        h8_to_f8(r_cur, xa);
        float term = 0.f;
#pragma unroll
        for (int k = 0; k < 8; k++) term += LRELU(xa[k] + xr[k]) * at[k];
        term += __shfl_xor_sync(0xffffffffu, term, 1);
        term += __shfl_xor_sync(0xffffffffu, term, 2);
        term += __shfl_xor_sync(0xffffffffu, term, 4);
        float a = v_cur ? __expf(term) : 0.f;
#pragma unroll
        for (int k = 0; k < 8; k++) acc[k] += a * xa[k];
        den += a;

        v_cur = v_nxt;
        r_cur = r_nxt;
    }
#pragma unroll
    for (int k = 0; k < 8; k++) {
        acc[k] += __shfl_xor_sync(0xffffffffu, acc[k], 8);
        acc[k] += __shfl_xor_sync(0xffffffffu, acc[k], 16);
    }
    den += __shfl_xor_sync(0xffffffffu, den, 8);
    den += __shfl_xor_sync(0xffffffffu, den, 16);
    float inv = 1.f / (den + 1e-16f);
    if (s == 0) {
#pragma unroll
        for (int k = 0; k < 8; k++) sout[h * 64 + c * 8 + k] = acc[k] * inv;
    }
    __syncthreads();

    int w = t >> 5, lane = t & 31;
    float val = 0.f;
    if (t < 64)
        val = 0.25f * (sout[t] + sout[t + 64] + sout[t + 128] + sout[t + 192]) + b1[t];

    float v = (t < 64) ? val : 0.f;
#pragma unroll
    for (int o = 16; o; o >>= 1) v += __shfl_xor_sync(0xffffffffu, v, o);
    if (lane == 0) red[w] = v;
    __syncthreads();
    float mu = (red[0] + red[1] + red[2] + red[3]) * (1.f / 64.f);
    float dd = (t < 64) ? (val - mu) : 0.f;
    float v2 = dd * dd;
#pragma unroll
    for (int o = 16; o; o >>= 1) v2 += __shfl_xor_sync(0xffffffffu, v2, o);
    if (lane == 0) red2[w] = v2;
    __syncthreads();
    float var = (red2[0] + red2[1] + red2[2] + red2[3]) * (1.f / 64.f);
    if (t < 64) {
        float y = dd * rsqrtf(var + 1e-5f) * lng[t] + lnb[t];
        float hv = fmaxf(y, 0.f);
        g_ah[(size_t)i * HID + t] = __float2half_rn(hv);   // only fp16 copy is consumed
    }
}

// ---------------- Layer 2 GAT: xl2 fp16 (ld 64), pipelined gather ----------
__global__ void gat2_kernel(const float* __restrict__ att2, const float* __restrict__ b2,
                            const float* __restrict__ lng, const float* __restrict__ lnb,
                            float* __restrict__ out, int Nn) {
    int w = threadIdx.x >> 5, l = threadIdx.x & 31;
    int i = blockIdx.x * 4 + w;
    if (i >= Nn) return;
    int s = l >> 3;
    int c = l & 7;
    const float* xr2 = g_xr1;                  // layer2 xr overlay (fp32, ld 64)

    const float* xrp = xr2 + (size_t)i * OUTD + c * 8;
    float4 xr0 = ((const float4*)xrp)[0];
    float4 xr1 = ((const float4*)xrp)[1];
    const float* atp = att2 + c * 8;
    float4 at0 = ((const float4*)atp)[0];
    float4 at1 = ((const float4*)atp)[1];
    float xr[8] = {xr0.x, xr0.y, xr0.z, xr0.w, xr1.x, xr1.y, xr1.z, xr1.w};
    float at[8] = {at0.x, at0.y, at0.z, at0.w, at1.x, at1.y, at1.z, at1.w};

    float acc[8] = {0.f, 0.f, 0.f, 0.f, 0.f, 0.f, 0.f, 0.f};
    float den = 0.f;
    int e0 = g_off[i], deg = g_off[i + 1] - e0;

    int v_cur = s < deg;
    int j_cur = v_cur ? __ldg(&g_src[e0 + s]) : 0;
    uint4 r_cur = *(const uint4*)(g_xlh + (size_t)j_cur * OUTD + c * 8);
    for (int base = 0; base < deg; base += 4) {
        int nb = base + 4;
        int v_nxt = (nb + s) < deg;
        int j_nxt = v_nxt ? __ldg(&g_src[e0 + nb + s]) : 0;
        uint4 r_nxt = *(const uint4*)(g_xlh + (size_t)j_nxt * OUTD + c * 8);

        float xa[8];
        h8_to_f8(r_cur, xa);
        float term = 0.f;
#pragma unroll
        for (int k = 0; k < 8; k++) term += LRELU(xa[k] + xr[k]) * at[k];
        term += __shfl_xor_sync(0xffffffffu, term, 1);
        term += __shfl_xor_sync(0xffffffffu, term, 2);
        term += __shfl_xor_sync(0xffffffffu, term, 4);
        float a = v_cur ? __expf(term) : 0.f;
#pragma unroll
        for (int k = 0; k < 8; k++) acc[k] += a * xa[k];
        den += a;

        v_cur = v_nxt;
        r_cur = r_nxt;
    }
#pragma unroll
    for (int k = 0; k < 8; k++) {
        acc[k] += __shfl_xor_sync(0xffffffffu, acc[k], 8);
        acc[k] += __shfl_xor_sync(0xffffffffu, acc[k], 16);
    }
    den += __shfl_xor_sync(0xffffffffu, den, 8);
    den += __shfl_xor_sync(0xffffffffu, den, 16);
    float inv = 1.f / (den + 1e-16f);

    const float* bp = b2 + c * 8;
    float4 bb0 = ((const float4*)bp)[0];
    float4 bb1 = ((const float4*)bp)[1];
    float bb[8] = {bb0.x, bb0.y, bb0.z, bb0.w, bb1.x, bb1.y, bb1.z, bb1.w};
    float v[8];
#pragma unroll
    for (int k = 0; k < 8; k++) v[k] = acc[k] * inv + bb[k];

    float sum = v[0] + v[1] + v[2] + v[3] + v[4] + v[5] + v[6] + v[7];
#pragma unroll
    for (int o = 16; o; o >>= 1) sum += __shfl_xor_sync(0xffffffffu, sum, o);
    float mu = sum * (1.f / 256.f);
    float q = 0.f;
    float d[8];
#pragma unroll
    for (int k = 0; k < 8; k++) { d[k] = v[k] - mu; q += d[k] * d[k]; }
#pragma unroll
    for (int o = 16; o; o >>= 1) q += __shfl_xor_sync(0xffffffffu, q, o);
    float var = q * (1.f / 256.f);
    float r = rsqrtf(var + 1e-5f);
    if (s == 0) {
        const float* gp = lng + c * 8;
        const float* np = lnb + c * 8;
        float4 gg0 = ((const float4*)gp)[0], gg1 = ((const float4*)gp)[1];
        float4 nn0 = ((const float4*)np)[0], nn1 = ((const float4*)np)[1];
        float4 o0, o1;
        o0.x = d[0] * r * gg0.x + nn0.x; o0.y = d[1] * r * gg0.y + nn0.y;
        o0.z = d[2] * r * gg0.z + nn0.z; o0.w = d[3] * r * gg0.w + nn0.w;
        o1.x = d[4] * r * gg1.x + nn1.x; o1.y = d[5] * r * gg1.y + nn1.y;
        o1.z = d[6] * r * gg1.z + nn1.z; o1.w = d[7] * r * gg1.w + nn1.w;
        float* op = out + (size_t)i * OUTD + c * 8;
        ((float4*)op)[0] = o0;
        ((float4*)op)[1] = o1;
    }
}

// ---------------- launch ----------------
extern "C" void kernel_launch(void* const* d_in, const int* in_sizes, int n_in,
                              void* d_out, int out_size) {
    const float* x    = (const float*)d_in[0];
    const int*   ei   = (const int*)d_in[1];
    const float* W1l  = (const float*)d_in[2];
    const float* W1r  = (const float*)d_in[3];
    const float* att1 = (const float*)d_in[4];
    const float* b1   = (const float*)d_in[5];
    const float* ln1g = (const float*)d_in[6];
    const float* ln1b = (const float*)d_in[7];
    const float* W2l  = (const float*)d_in[8];
    const float* W2r  = (const float*)d_in[9];
    const float* att2 = (const float*)d_in[10];
    const float* b2   = (const float*)d_in[11];
    const float* ln2g = (const float*)d_in[12];
    const float* ln2b = (const float*)d_in[13];
    float* out = (float*)d_out;

    int N = in_sizes[0] / IN_DIM;
    int E = in_sizes[1] / 2;
    if (N > NMAX) N = NMAX;
    if (E > EMAX) E = EMAX;
    int ETOT_RT = E + N;
    int nscan = (N + SCAN_BLK - 1) / SCAN_BLK;

    float* p_xr1;
    __half *p_xlh, *p_ah, *p_bh, *p_bh2;
    cudaGetSymbolAddress((void**)&p_xr1, g_xr1);
    cudaGetSymbolAddress((void**)&p_xlh, g_xlh);
    cudaGetSymbolAddress((void**)&p_ah,  g_ah);
    cudaGetSymbolAddress((void**)&p_bh,  g_bh);
    cudaGetSymbolAddress((void**)&p_bh2, g_bh2);

    cudaFuncSetAttribute(hgemm_kernel<16>, cudaFuncAttributeMaxDynamicSharedMemorySize, HG_SMEM_BYTES);
    cudaFuncSetAttribute(hgemm_kernel<4>,  cudaFuncAttributeMaxDynamicSharedMemorySize, HG_SMEM_BYTES);

    static cudaStream_t s2 = nullptr;
    static cudaEvent_t ev_fork = nullptr, ev_g1 = nullptr;
    if (!s2) {
        cudaStreamCreateWithFlags(&s2, cudaStreamNonBlocking);
        cudaEventCreateWithFlags(&ev_fork, cudaEventDisableTiming);
        cudaEventCreateWithFlags(&ev_g1, cudaEventDisableTiming);
    }

    cudaEventRecord(ev_fork, 0);
    cudaStreamWaitEvent(s2, ev_fork, 0);

    // ---- stream s2: layer-1 GEMM chain (fp16; xl1 -> fp16, xr1 -> fp32) ----
    {
        int n4 = N * IN_DIM / 4;
        conv_h_kernel<<<(n4 + 255) / 256, 256, 0, s2>>>(x, p_ah, n4);
        pack_bt_h_kernel<<<(512 * 256 + 255) / 256, 256, 0, s2>>>(W1l, W1r, p_bh, 256, 256);
        pack_bt_h_kernel<<<(128 * 64 + 255) / 256, 256, 0, s2>>>(W2l, W2r, p_bh2, 64, 64);
        dim3 grid(4, (N + 127) / 128);
        hgemm_kernel<16><<<grid, 256, HG_SMEM_BYTES, s2>>>(p_ah, p_bh, p_xlh, p_xr1, N, 256, 256);
        cudaEventRecord(ev_g1, s2);
    }

    // ---- default stream: CSR build (concurrent) ----
    zero_deg_kernel<<<(N + 256) / 256, 256>>>(N);
    hist_kernel<<<(ETOT_RT + 255) / 256, 256>>>(ei, E, N);
    scan1_kernel<<<nscan, SCAN_BLK>>>(N);
    scan2_kernel<<<1, 64>>>(nscan, N);
    scan3_kernel<<<nscan, SCAN_BLK>>>(N);
    scatter_kernel<<<(ETOT_RT + 255) / 256, 256>>>(ei, E, N);

    cudaStreamWaitEvent(0, ev_g1, 0);

    gat1_kernel<<<N, 128>>>(att1, b1, ln1g, ln1b, N);

    // Layer 2 GEMM: xl2 -> fp16 (g_xlh, ld 64), xr2 -> fp32 (g_xr1, ld 64)
    {
        dim3 grid(1, (N + 127) / 128);
        hgemm_kernel<4><<<grid, 256, HG_SMEM_BYTES>>>(p_ah, p_bh2, p_xlh, p_xr1, N, 64, 64);
    }

    gat2_kernel<<<(N + 3) / 4, 128>>>(att2, b2, ln2g, ln2b, out, N);
}